// round 15
// baseline (speedup 1.0000x reference)
#include <cuda_runtime.h>
#include <cuda_bf16.h>
#include <cstdint>

// Problem constants
#define Bb 2
#define Nn 1024
#define Ee 8192
#define Dd 64
#define NT8 8            // 8 tiles of 128 along N
#define PAIRS8 36        // upper-triangular tile pairs
#define KC 32            // K elements per stage
#define KSPLIT 4
#define KQ (Ee / KSPLIT)           // 2048
#define NCHUNK (KQ / KC)           // 64

// ---------------------------------------------------------------------------
// Device scratch
// ---------------------------------------------------------------------------
__device__ float g_scale[Bb * Ee];
__device__ float g_hw[Bb * Nn * Dd];
__device__ float g_part[(size_t)Bb * PAIRS8 * KSPLIT * 128 * 128];
__device__ float g_outp16[16][Bb * Nn * Dd];

// ---------------------------------------------------------------------------
// Portable PTX helpers
// ---------------------------------------------------------------------------
__device__ __forceinline__ uint32_t smem_u32(const void* p) {
    uint32_t a;
    asm("{ .reg .u64 t; cvta.to.shared.u64 t, %1; cvt.u32.u64 %0, t; }" : "=r"(a) : "l"(p));
    return a;
}
#define CP16(dst, src) \
    asm volatile("cp.async.cg.shared.global [%0], [%1], 16;" :: "r"(dst), "l"(src))
#define CP_COMMIT() asm volatile("cp.async.commit_group;")
#define CP_WAIT0()  asm volatile("cp.async.wait_group 0;")
#define CP_WAIT1()  asm volatile("cp.async.wait_group 1;")

__device__ __forceinline__ void ldsm4(uint32_t* r, uint32_t addr) {
    asm volatile("ldmatrix.sync.aligned.m8n8.x4.shared.b16 {%0,%1,%2,%3}, [%4];"
                 : "=r"(r[0]), "=r"(r[1]), "=r"(r[2]), "=r"(r[3]) : "r"(addr));
}
__device__ __forceinline__ void mma_tf32(float* c, const uint32_t* a, const uint32_t* b) {
    asm volatile(
        "mma.sync.aligned.m16n8k8.row.col.f32.tf32.tf32.f32 "
        "{%0,%1,%2,%3}, {%4,%5,%6,%7}, {%8,%9}, {%0,%1,%2,%3};"
        : "+f"(c[0]), "+f"(c[1]), "+f"(c[2]), "+f"(c[3])
        : "r"(a[0]), "r"(a[1]), "r"(a[2]), "r"(a[3]), "r"(b[0]), "r"(b[1]));
}

// ---------------------------------------------------------------------------
// pre_kernel: fused scale (blocks 0..63) + HW = H_v@W (blocks 64..575)
// ---------------------------------------------------------------------------
__global__ void pre_kernel(const float* __restrict__ H_e,
                           const float* __restrict__ p,
                           const float* __restrict__ H_v,
                           const float* __restrict__ W) {
    __shared__ float sm[64 * 64 + 4 * 64];
    int bid = blockIdx.x, tid = threadIdx.x;
    if (bid < 64) {
        if (tid < 64) sm[tid] = p[tid];
        __syncthreads();
        int r = bid * 256 + tid;
        const float4* he = reinterpret_cast<const float4*>(H_e + (size_t)r * 64);
        float s = 0.f;
#pragma unroll
        for (int i = 0; i < 16; i++) {
            float4 v = he[i];
            s += v.x * sm[i * 4 + 0] + v.y * sm[i * 4 + 1] +
                 v.z * sm[i * 4 + 2] + v.w * sm[i * 4 + 3];
        }
        g_scale[r] = s;
    } else {
        float* ws = sm;
        float* hv = sm + 64 * 64;
        int tx = tid & 63, ty = tid >> 6;
        for (int i = tid; i < 64 * 64; i += 256) ws[i] = W[i];
        int row0 = (bid - 64) * 4;
        hv[ty * 64 + tx] = H_v[(size_t)(row0 + ty) * 64 + tx];
        __syncthreads();
        float acc = 0.f;
#pragma unroll
        for (int k = 0; k < 64; k++) acc += hv[ty * 64 + k] * ws[k * 64 + tx];
        g_hw[(size_t)(row0 + ty) * 64 + tx] = acc;
    }
}

// ---------------------------------------------------------------------------
// mult partial (R13-proven, unchanged): 128x128 tile, quarter-K per CTA,
// tf32 m16n8k8, raw f32 T both tiles, per-k scale on A fragments in regs.
// ---------------------------------------------------------------------------
#define STRIDE_W 36
#define STAGE_WORDS (128 * STRIDE_W)           // per array: 4608 words
#define OFF_B_BYTES (STAGE_WORDS * 4)          // 18432
#define OFF_S_BYTES (2 * STAGE_WORDS * 4)      // 36864 (32-float s block)
#define STAGE_BYTES (OFF_S_BYTES + 128)        // 36992
#define MULT_SMEM (3 * STAGE_BYTES)            // 110976
#define ROWB (STRIDE_W * 4)                    // 144 bytes per row
#define MTSTEP (16 * ROWB)                     // 2304 bytes per 16-row block

__global__ void __launch_bounds__(256, 2)
mult_partial(const float* __restrict__ T) {
    extern __shared__ __align__(16) char smraw[];
    uint32_t stg = smem_u32(smraw);

    int tid = threadIdx.x;
    int wid = tid >> 5;
    int lid = tid & 31;
    int wm = wid & 1;
    int wn = wid >> 1;

    int p2 = blockIdx.x;
    int pair = p2 >> 2;
    int ksp = p2 & 3;
    int b = pair / PAIRS8;
    int t = pair % PAIRS8;
    int ti = 0, rem = t;
    while (rem >= NT8 - ti) { rem -= NT8 - ti; ti++; }
    int tj = ti + rem;

    size_t rowA = (size_t)(b * Nn + ti * 128);
    size_t rowB = (size_t)(b * Nn + tj * 128);
    int kbase = ksp * KQ;
    const float* scg = g_scale + b * Ee;

    auto load_stage = [&](int sidx, int k0) {
        uint32_t sb = stg + sidx * STAGE_BYTES;
#pragma unroll
        for (int i = 0; i < 4; i++) {
            int chunk = tid + i * 256;
            int row = chunk >> 3, cc = chunk & 7;
            uint32_t d = (uint32_t)(row * ROWB + cc * 16);
            CP16(sb + d, T + (rowA + row) * (size_t)Ee + k0 + cc * 4);
            CP16(sb + OFF_B_BYTES + d, T + (rowB + row) * (size_t)Ee + k0 + cc * 4);
        }
        if (tid < 8)
            CP16(sb + OFF_S_BYTES + tid * 16, scg + k0 + tid * 4);
        CP_COMMIT();
    };

    float acc[4][4][4];
#pragma unroll
    for (int i = 0; i < 4; i++)
#pragma unroll
        for (int j = 0; j < 4; j++)
#pragma unroll
            for (int q = 0; q < 4; q++) acc[i][j][q] = 0.f;

    load_stage(0, kbase);
    load_stage(1, kbase + KC);

    uint32_t a_lane = (uint32_t)(((lid & 7) + ((lid >> 3) & 1) * 8) * ROWB +
                                 (lid >> 4) * 16);
    uint32_t b_lane = (uint32_t)((((lid >> 4) * 8) + (lid & 7)) * ROWB +
                                 (((lid >> 3) & 1) * 16));
    uint32_t a_base0 = (uint32_t)(wm * 64 * ROWB) + a_lane;
    uint32_t b_base0 = (uint32_t)OFF_B_BYTES + (uint32_t)(wn * 32 * ROWB) + b_lane;
    int skc = lid & 3;

    for (int s = 0; s < NCHUNK; s++) {
        if (s < NCHUNK - 1) CP_WAIT1(); else CP_WAIT0();
        __syncthreads();
        uint32_t sb = stg + (s % 3) * STAGE_BYTES;
        uint32_t ab = sb + a_base0;
        uint32_t bb = sb + b_base0;
        const float* sS = reinterpret_cast<const float*>(
            smraw + (size_t)(sb - stg) + OFF_S_BYTES);

#pragma unroll
        for (int ks = 0; ks < 4; ks++) {
            float sv0 = sS[ks * 8 + skc];
            float sv1 = sS[ks * 8 + 4 + skc];
            uint32_t af[4][4], bq[2][4];
#pragma unroll
            for (int mt = 0; mt < 4; mt++)
                ldsm4(af[mt], ab + mt * MTSTEP + ks * 32);
#pragma unroll
            for (int ntp = 0; ntp < 2; ntp++)
                ldsm4(bq[ntp], bb + ntp * MTSTEP + ks * 32);
#pragma unroll
            for (int mt = 0; mt < 4; mt++) {
                af[mt][0] = __float_as_uint(__uint_as_float(af[mt][0]) * sv0);
                af[mt][1] = __float_as_uint(__uint_as_float(af[mt][1]) * sv0);
                af[mt][2] = __float_as_uint(__uint_as_float(af[mt][2]) * sv1);
                af[mt][3] = __float_as_uint(__uint_as_float(af[mt][3]) * sv1);
            }
#pragma unroll
            for (int mt = 0; mt < 4; mt++)
#pragma unroll
                for (int nt = 0; nt < 4; nt++)
                    mma_tf32(acc[mt][nt], af[mt], &bq[nt >> 1][(nt & 1) * 2]);
        }
        if (s + 2 < NCHUNK) load_stage((s + 2) % 3, kbase + (s + 2) * KC);
    }

    float* pt = g_part + (size_t)p2 * 128 * 128;
#pragma unroll
    for (int mt = 0; mt < 4; mt++)
#pragma unroll
        for (int nt = 0; nt < 4; nt++) {
            int r = wm * 64 + mt * 16 + (lid >> 2);
            int c = wn * 32 + nt * 8 + (lid & 3) * 2;
            *reinterpret_cast<float2*>(pt + (size_t)r * 128 + c) =
                make_float2(acc[mt][nt][0], acc[mt][nt][1]);
            *reinterpret_cast<float2*>(pt + (size_t)(r + 8) * 128 + c) =
                make_float2(acc[mt][nt][2], acc[mt][nt][3]);
        }
}

// ---------------------------------------------------------------------------
// combine_out: per (b, i, rh, j, kh): 64-row x 64-k sub-tile of ordered
// tile (i,j): v = mask(sum of 4 partials) * adj_v;
// out16[slot j*2+kh][rows i*128+rh*64 ..] += v @ HW[j-block k-half].
// grid = Bb*16*8*2 = 512, 256 threads (4x4 out/thread), smem 34.8 KB
// -> ~5-6 CTAs/SM for latency hiding.
// ---------------------------------------------------------------------------
#define CO_SMEM (2 * 64 * 68 * 4)              // 34816

__global__ void __launch_bounds__(256)
combine_out(const float* __restrict__ adj_v) {
    extern __shared__ float cs[];
    float* vs = cs;                      // [k][r] stride 68 (k,r in 0..63)
    float* HWs = cs + 64 * 68;           // [k][d] stride 68

    int tid = threadIdx.x;
    int bid = blockIdx.x;
    int b = bid >> 8;
    int rr = bid & 255;
    int i2 = rr >> 4;                    // 0..15
    int j = (rr >> 1) & 7;
    int kh = rr & 1;
    int i = i2 >> 1, rh = i2 & 1;

    // HW rows j*128 + kh*64 .. +64
    const float* HWb = g_hw + (size_t)b * Nn * Dd + (size_t)(j * 128 + kh * 64) * 64;
    for (int idx = tid; idx < 4096; idx += 256)
        HWs[(idx >> 6) * 68 + (idx & 63)] = HWb[idx];

    int lo = i < j ? i : j, hi = i < j ? j : i;
    int p = 8 * lo - lo * (lo - 1) / 2 + (hi - lo);
    const float* p0 = g_part + ((size_t)(b * PAIRS8 + p) * 4 + 0) * 16384;
    const float* p1 = g_part + ((size_t)(b * PAIRS8 + p) * 4 + 1) * 16384;
    const float* p2 = g_part + ((size_t)(b * PAIRS8 + p) * 4 + 2) * 16384;
    const float* p3 = g_part + ((size_t)(b * PAIRS8 + p) * 4 + 3) * 16384;

    if (i <= j) {
        // v[r][k] = m[rh*64+r][kh*64+k]
        for (int idx = tid; idx < 4096; idx += 256) {
            int r = idx >> 6, k = idx & 63;
            int src = (rh * 64 + r) * 128 + kh * 64 + k;
            vs[k * 68 + r] = (p0[src] + p1[src]) + (p2[src] + p3[src]);
        }
    } else {
        // v[r][k] = m[kh*64+k][rh*64+r]
        for (int idx = tid; idx < 4096; idx += 256) {
            int k = idx >> 6, r = idx & 63;
            int src = (kh * 64 + k) * 128 + rh * 64 + r;
            vs[k * 68 + r] = (p0[src] + p1[src]) + (p2[src] + p3[src]);
        }
    }
    __syncthreads();

    // mask + adj multiply: element (r, c) -> global (n, mcol)
    const float* av = adj_v + (size_t)b * Nn * Nn;
    for (int idx = tid; idx < 4096; idx += 256) {
        int r = idx >> 6, c = idx & 63;
        int n = i * 128 + rh * 64 + r;
        int mcol = j * 128 + kh * 64 + c;
        float m = vs[c * 68 + r];
        if (n == mcol) m = 1.f;
        vs[c * 68 + r] = m * av[(size_t)n * Nn + mcol];
    }
    __syncthreads();

    int rq = tid & 15;          // rows rq*4 .. +3
    int cq = tid >> 4;          // cols cq*4 .. +3
    float o[4][4];
#pragma unroll
    for (int r = 0; r < 4; r++)
#pragma unroll
        for (int c = 0; c < 4; c++) o[r][c] = 0.f;

    for (int k = 0; k < 64; k++) {
        float4 h = *reinterpret_cast<float4*>(&HWs[k * 68 + cq * 4]);
        float4 v = *reinterpret_cast<float4*>(&vs[k * 68 + rq * 4]);
        float vv[4] = {v.x, v.y, v.z, v.w};
#pragma unroll
        for (int r = 0; r < 4; r++) {
            o[r][0] += vv[r] * h.x; o[r][1] += vv[r] * h.y;
            o[r][2] += vv[r] * h.z; o[r][3] += vv[r] * h.w;
        }
    }

    float* os = g_outp16[j * 2 + kh] + ((size_t)b * Nn + i * 128 + rh * 64) * 64;
#pragma unroll
    for (int r = 0; r < 4; r++)
        *reinterpret_cast<float4*>(&os[(size_t)(rq * 4 + r) * 64 + cq * 4]) =
            make_float4(o[r][0], o[r][1], o[r][2], o[r][3]);
}

// ---------------------------------------------------------------------------
// out_reduce: sum 16 slots + bias, and copy the H_e pass-through output.
// ---------------------------------------------------------------------------
#define OUT_ELEMS (Bb * Nn * Dd)               // 131072
#define HE_ELEMS (Bb * Ee * 64)                // 1048576

__global__ void out_reduce(const float* __restrict__ bias,
                           const float* __restrict__ H_e,
                           float* __restrict__ out, int do_he) {
    int idx = blockIdx.x * 256 + threadIdx.x;
    if (idx < OUT_ELEMS) {
        float s = bias[idx & 63];
#pragma unroll
        for (int q = 0; q < 16; q++) s += g_outp16[q][idx];
        out[idx] = s;
    } else if (do_he) {
        int jdx = idx - OUT_ELEMS;
        if (jdx < HE_ELEMS) out[OUT_ELEMS + jdx] = H_e[jdx];
    }
}

// ---------------------------------------------------------------------------
extern "C" void kernel_launch(void* const* d_in, const int* in_sizes, int n_in,
                              void* d_out, int out_size) {
    const float* H_v   = (const float*)d_in[0];
    const float* H_e   = (const float*)d_in[1];
    // d_in[2] = adj_e : unused by the reference math
    const float* adj_v = (const float*)d_in[3];
    const float* T     = (const float*)d_in[4];
    const float* W     = (const float*)d_in[5];
    const float* p     = (const float*)d_in[6];
    const float* bias  = (const float*)d_in[7];
    float* out = (float*)d_out;

    static bool attr_set = false;
    if (!attr_set) {
        cudaFuncSetAttribute(mult_partial, cudaFuncAttributeMaxDynamicSharedMemorySize,
                             MULT_SMEM);
        cudaFuncSetAttribute(combine_out, cudaFuncAttributeMaxDynamicSharedMemorySize,
                             CO_SMEM);
        attr_set = true;
    }

    pre_kernel<<<576, 256>>>(H_e, p, H_v, W);
    mult_partial<<<Bb * PAIRS8 * KSPLIT, 256, MULT_SMEM>>>(T);
    combine_out<<<Bb * 256, 256, CO_SMEM>>>(adj_v);

    int do_he = ((long long)out_size >= (long long)OUT_ELEMS + HE_ELEMS) ? 1 : 0;
    int total = do_he ? (OUT_ELEMS + HE_ELEMS) : OUT_ELEMS;
    out_reduce<<<(total + 255) / 256, 256>>>(bias, H_e, out, do_he);
}

// round 16
// speedup vs baseline: 1.0447x; 1.0447x over previous
#include <cuda_runtime.h>
#include <cuda_bf16.h>
#include <cstdint>

// Problem constants
#define Bb 2
#define Nn 1024
#define Ee 8192
#define Dd 64
#define NT8 8            // 8 tiles of 128 along N
#define PAIRS8 36        // upper-triangular tile pairs
#define KC 32            // K elements per stage
#define KSPLIT 4
#define KQ (Ee / KSPLIT)           // 2048
#define NCHUNK (KQ / KC)           // 64

// ---------------------------------------------------------------------------
// Device scratch
// ---------------------------------------------------------------------------
__device__ float g_scale[Bb * Ee];
__device__ float g_hw[Bb * Nn * Dd];
__device__ float g_part[(size_t)Bb * PAIRS8 * KSPLIT * 128 * 128];
__device__ float g_outp16[16][Bb * Nn * Dd];

// ---------------------------------------------------------------------------
// Portable PTX helpers
// ---------------------------------------------------------------------------
__device__ __forceinline__ uint32_t smem_u32(const void* p) {
    uint32_t a;
    asm("{ .reg .u64 t; cvta.to.shared.u64 t, %1; cvt.u32.u64 %0, t; }" : "=r"(a) : "l"(p));
    return a;
}
#define CP16(dst, src) \
    asm volatile("cp.async.cg.shared.global [%0], [%1], 16;" :: "r"(dst), "l"(src))
#define CP_COMMIT() asm volatile("cp.async.commit_group;")
#define CP_WAIT0()  asm volatile("cp.async.wait_group 0;")
#define CP_WAIT1()  asm volatile("cp.async.wait_group 1;")

__device__ __forceinline__ void ldsm4(uint32_t* r, uint32_t addr) {
    asm volatile("ldmatrix.sync.aligned.m8n8.x4.shared.b16 {%0,%1,%2,%3}, [%4];"
                 : "=r"(r[0]), "=r"(r[1]), "=r"(r[2]), "=r"(r[3]) : "r"(addr));
}
__device__ __forceinline__ void mma_tf32(float* c, const uint32_t* a, const uint32_t* b) {
    asm volatile(
        "mma.sync.aligned.m16n8k8.row.col.f32.tf32.tf32.f32 "
        "{%0,%1,%2,%3}, {%4,%5,%6,%7}, {%8,%9}, {%0,%1,%2,%3};"
        : "+f"(c[0]), "+f"(c[1]), "+f"(c[2]), "+f"(c[3])
        : "r"(a[0]), "r"(a[1]), "r"(a[2]), "r"(a[3]), "r"(b[0]), "r"(b[1]));
}

// ---------------------------------------------------------------------------
// pre_kernel: fused scale (blocks 0..63) + HW = H_v@W (blocks 64..575)
// ---------------------------------------------------------------------------
__global__ void pre_kernel(const float* __restrict__ H_e,
                           const float* __restrict__ p,
                           const float* __restrict__ H_v,
                           const float* __restrict__ W) {
    __shared__ float sm[64 * 64 + 4 * 64];
    int bid = blockIdx.x, tid = threadIdx.x;
    if (bid < 64) {
        if (tid < 64) sm[tid] = p[tid];
        __syncthreads();
        int r = bid * 256 + tid;
        const float4* he = reinterpret_cast<const float4*>(H_e + (size_t)r * 64);
        float s = 0.f;
#pragma unroll
        for (int i = 0; i < 16; i++) {
            float4 v = he[i];
            s += v.x * sm[i * 4 + 0] + v.y * sm[i * 4 + 1] +
                 v.z * sm[i * 4 + 2] + v.w * sm[i * 4 + 3];
        }
        g_scale[r] = s;
    } else {
        float* ws = sm;
        float* hv = sm + 64 * 64;
        int tx = tid & 63, ty = tid >> 6;
        for (int i = tid; i < 64 * 64; i += 256) ws[i] = W[i];
        int row0 = (bid - 64) * 4;
        hv[ty * 64 + tx] = H_v[(size_t)(row0 + ty) * 64 + tx];
        __syncthreads();
        float acc = 0.f;
#pragma unroll
        for (int k = 0; k < 64; k++) acc += hv[ty * 64 + k] * ws[k * 64 + tx];
        g_hw[(size_t)(row0 + ty) * 64 + tx] = acc;
    }
}

// ---------------------------------------------------------------------------
// mult partial: 128x128 tile, quarter-K per CTA, tf32 m16n8k8.
// Raw f32 T for both tiles; per-k scale applied to the B FRAGMENTS in
// registers (8 FMUL/ks vs 16 for A-side — b0 regs carry k=ks*8+(lane&3),
// b1 regs carry k+4, identical sv0/sv1 broadcasts).
// grid = Bb*PAIRS8*KSPLIT = 288 (~2 CTAs/SM), 256 threads, warp grid 2x4.
// ---------------------------------------------------------------------------
#define STRIDE_W 36
#define STAGE_WORDS (128 * STRIDE_W)           // per array: 4608 words
#define OFF_B_BYTES (STAGE_WORDS * 4)          // 18432
#define OFF_S_BYTES (2 * STAGE_WORDS * 4)      // 36864 (32-float s block)
#define STAGE_BYTES (OFF_S_BYTES + 128)        // 36992
#define MULT_SMEM (3 * STAGE_BYTES)            // 110976
#define ROWB (STRIDE_W * 4)                    // 144 bytes per row
#define MTSTEP (16 * ROWB)                     // 2304 bytes per 16-row block

__global__ void __launch_bounds__(256, 2)
mult_partial(const float* __restrict__ T) {
    extern __shared__ __align__(16) char smraw[];
    uint32_t stg = smem_u32(smraw);

    int tid = threadIdx.x;
    int wid = tid >> 5;
    int lid = tid & 31;
    int wm = wid & 1;
    int wn = wid >> 1;

    int p2 = blockIdx.x;
    int pair = p2 >> 2;
    int ksp = p2 & 3;
    int b = pair / PAIRS8;
    int t = pair % PAIRS8;
    int ti = 0, rem = t;
    while (rem >= NT8 - ti) { rem -= NT8 - ti; ti++; }
    int tj = ti + rem;

    size_t rowA = (size_t)(b * Nn + ti * 128);
    size_t rowB = (size_t)(b * Nn + tj * 128);
    int kbase = ksp * KQ;
    const float* scg = g_scale + b * Ee;

    auto load_stage = [&](int sidx, int k0) {
        uint32_t sb = stg + sidx * STAGE_BYTES;
#pragma unroll
        for (int i = 0; i < 4; i++) {
            int chunk = tid + i * 256;
            int row = chunk >> 3, cc = chunk & 7;
            uint32_t d = (uint32_t)(row * ROWB + cc * 16);
            CP16(sb + d, T + (rowA + row) * (size_t)Ee + k0 + cc * 4);
            CP16(sb + OFF_B_BYTES + d, T + (rowB + row) * (size_t)Ee + k0 + cc * 4);
        }
        if (tid < 8)
            CP16(sb + OFF_S_BYTES + tid * 16, scg + k0 + tid * 4);
        CP_COMMIT();
    };

    float acc[4][4][4];
#pragma unroll
    for (int i = 0; i < 4; i++)
#pragma unroll
        for (int j = 0; j < 4; j++)
#pragma unroll
            for (int q = 0; q < 4; q++) acc[i][j][q] = 0.f;

    load_stage(0, kbase);
    load_stage(1, kbase + KC);

    uint32_t a_lane = (uint32_t)(((lid & 7) + ((lid >> 3) & 1) * 8) * ROWB +
                                 (lid >> 4) * 16);
    uint32_t b_lane = (uint32_t)((((lid >> 4) * 8) + (lid & 7)) * ROWB +
                                 (((lid >> 3) & 1) * 16));
    uint32_t a_base0 = (uint32_t)(wm * 64 * ROWB) + a_lane;
    uint32_t b_base0 = (uint32_t)OFF_B_BYTES + (uint32_t)(wn * 32 * ROWB) + b_lane;
    int skc = lid & 3;

    for (int s = 0; s < NCHUNK; s++) {
        if (s < NCHUNK - 1) CP_WAIT1(); else CP_WAIT0();
        __syncthreads();
        uint32_t sb = stg + (s % 3) * STAGE_BYTES;
        uint32_t ab = sb + a_base0;
        uint32_t bb = sb + b_base0;
        const float* sS = reinterpret_cast<const float*>(
            smraw + (size_t)(sb - stg) + OFF_S_BYTES);

#pragma unroll
        for (int ks = 0; ks < 4; ks++) {
            float sv0 = sS[ks * 8 + skc];
            float sv1 = sS[ks * 8 + 4 + skc];
            uint32_t af[4][4], bq[2][4];
#pragma unroll
            for (int mt = 0; mt < 4; mt++)
                ldsm4(af[mt], ab + mt * MTSTEP + ks * 32);
#pragma unroll
            for (int ntp = 0; ntp < 2; ntp++)
                ldsm4(bq[ntp], bb + ntp * MTSTEP + ks * 32);
            // scale B fragments in registers: regs 0,2 carry k -> sv0;
            // regs 1,3 carry k+4 -> sv1. (8 FMULs vs 16 on the A side.)
#pragma unroll
            for (int ntp = 0; ntp < 2; ntp++) {
                bq[ntp][0] = __float_as_uint(__uint_as_float(bq[ntp][0]) * sv0);
                bq[ntp][1] = __float_as_uint(__uint_as_float(bq[ntp][1]) * sv1);
                bq[ntp][2] = __float_as_uint(__uint_as_float(bq[ntp][2]) * sv0);
                bq[ntp][3] = __float_as_uint(__uint_as_float(bq[ntp][3]) * sv1);
            }
#pragma unroll
            for (int mt = 0; mt < 4; mt++)
#pragma unroll
                for (int nt = 0; nt < 4; nt++)
                    mma_tf32(acc[mt][nt], af[mt], &bq[nt >> 1][(nt & 1) * 2]);
        }
        if (s + 2 < NCHUNK) load_stage((s + 2) % 3, kbase + (s + 2) * KC);
    }

    float* pt = g_part + (size_t)p2 * 128 * 128;
#pragma unroll
    for (int mt = 0; mt < 4; mt++)
#pragma unroll
        for (int nt = 0; nt < 4; nt++) {
            int r = wm * 64 + mt * 16 + (lid >> 2);
            int c = wn * 32 + nt * 8 + (lid & 3) * 2;
            *reinterpret_cast<float2*>(pt + (size_t)r * 128 + c) =
                make_float2(acc[mt][nt][0], acc[mt][nt][1]);
            *reinterpret_cast<float2*>(pt + (size_t)(r + 8) * 128 + c) =
                make_float2(acc[mt][nt][2], acc[mt][nt][3]);
        }
}

// ---------------------------------------------------------------------------
// combine_out (R14-proven): per (b, i, j, kh): k-half kh of ordered tile
// (i,j): v = mask(sum of 4 partials) * adj_v; out16[slot j*2+kh][rows
// i*128..] = v_half @ HW[j-block k-half]. grid = Bb*64*2 = 256, 512 thr.
// smem: vs[64][132] + HWs[64][68] -> 2 CTAs/SM.
// ---------------------------------------------------------------------------
#define CO_SMEM (64 * 132 * 4 + 64 * 68 * 4)

__global__ void __launch_bounds__(512, 2)
combine_out(const float* __restrict__ adj_v) {
    extern __shared__ float cs[];
    float* vs = cs;                      // [k][r] stride 132 (k local 0..63)
    float* HWs = cs + 64 * 132;          // [k][d] stride 68

    int tid = threadIdx.x;
    int bid = blockIdx.x;
    int b = bid >> 7;
    int r2 = bid & 127;
    int ij = r2 >> 1, kh = r2 & 1;
    int i = ij >> 3, j = ij & 7;

    const float* HWb = g_hw + (size_t)b * Nn * Dd + (size_t)(j * 128 + kh * 64) * 64;
    for (int idx = tid; idx < 4096; idx += 512)
        HWs[(idx >> 6) * 68 + (idx & 63)] = HWb[idx];

    int lo = i < j ? i : j, hi = i < j ? j : i;
    int p = 8 * lo - lo * (lo - 1) / 2 + (hi - lo);
    const float* p0 = g_part + ((size_t)(b * PAIRS8 + p) * 4 + 0) * 16384;
    const float* p1 = g_part + ((size_t)(b * PAIRS8 + p) * 4 + 1) * 16384;
    const float* p2 = g_part + ((size_t)(b * PAIRS8 + p) * 4 + 2) * 16384;
    const float* p3 = g_part + ((size_t)(b * PAIRS8 + p) * 4 + 3) * 16384;

    if (i <= j) {
        for (int idx = tid; idx < 8192; idx += 512) {
            int r = idx >> 6, c = idx & 63;
            int src = r * 128 + kh * 64 + c;
            vs[c * 132 + r] = (p0[src] + p1[src]) + (p2[src] + p3[src]);
        }
    } else {
        for (int idx = tid; idx < 8192; idx += 512) {
            int rp = idx >> 7, cp = idx & 127;
            int src = (kh * 64 + rp) * 128 + cp;
            vs[rp * 132 + cp] = (p0[src] + p1[src]) + (p2[src] + p3[src]);
        }
    }
    __syncthreads();

    const float* av = adj_v + (size_t)b * Nn * Nn;
    for (int idx = tid; idx < 8192; idx += 512) {
        int r = idx >> 6, c = idx & 63;
        int n = i * 128 + r, mcol = j * 128 + kh * 64 + c;
        float m = vs[c * 132 + r];
        if (i == j && r == kh * 64 + c) m = 1.f;
        vs[c * 132 + r] = m * av[(size_t)n * Nn + mcol];
    }
    __syncthreads();

    int rq = tid & 31;          // rows rq*4 .. +3
    int cq = tid >> 5;          // cols cq*4 .. +3
    float o[4][4];
#pragma unroll
    for (int r = 0; r < 4; r++)
#pragma unroll
        for (int c = 0; c < 4; c++) o[r][c] = 0.f;

    for (int k = 0; k < 64; k++) {
        float4 h = *reinterpret_cast<float4*>(&HWs[k * 68 + cq * 4]);
        float4 v = *reinterpret_cast<float4*>(&vs[k * 132 + rq * 4]);
        float vv[4] = {v.x, v.y, v.z, v.w};
#pragma unroll
        for (int r = 0; r < 4; r++) {
            o[r][0] += vv[r] * h.x; o[r][1] += vv[r] * h.y;
            o[r][2] += vv[r] * h.z; o[r][3] += vv[r] * h.w;
        }
    }

    float* os = g_outp16[j * 2 + kh] + ((size_t)b * Nn + i * 128) * 64;
#pragma unroll
    for (int r = 0; r < 4; r++)
        *reinterpret_cast<float4*>(&os[(size_t)(rq * 4 + r) * 64 + cq * 4]) =
            make_float4(o[r][0], o[r][1], o[r][2], o[r][3]);
}

// ---------------------------------------------------------------------------
// out_reduce: sum 16 slots + bias, and copy the H_e pass-through output.
// ---------------------------------------------------------------------------
#define OUT_ELEMS (Bb * Nn * Dd)               // 131072
#define HE_ELEMS (Bb * Ee * 64)                // 1048576

__global__ void out_reduce(const float* __restrict__ bias,
                           const float* __restrict__ H_e,
                           float* __restrict__ out, int do_he) {
    int idx = blockIdx.x * 256 + threadIdx.x;
    if (idx < OUT_ELEMS) {
        float s = bias[idx & 63];
#pragma unroll
        for (int q = 0; q < 16; q++) s += g_outp16[q][idx];
        out[idx] = s;
    } else if (do_he) {
        int jdx = idx - OUT_ELEMS;
        if (jdx < HE_ELEMS) out[OUT_ELEMS + jdx] = H_e[jdx];
    }
}

// ---------------------------------------------------------------------------
extern "C" void kernel_launch(void* const* d_in, const int* in_sizes, int n_in,
                              void* d_out, int out_size) {
    const float* H_v   = (const float*)d_in[0];
    const float* H_e   = (const float*)d_in[1];
    // d_in[2] = adj_e : unused by the reference math
    const float* adj_v = (const float*)d_in[3];
    const float* T     = (const float*)d_in[4];
    const float* W     = (const float*)d_in[5];
    const float* p     = (const float*)d_in[6];
    const float* bias  = (const float*)d_in[7];
    float* out = (float*)d_out;

    static bool attr_set = false;
    if (!attr_set) {
        cudaFuncSetAttribute(mult_partial, cudaFuncAttributeMaxDynamicSharedMemorySize,
                             MULT_SMEM);
        cudaFuncSetAttribute(combine_out, cudaFuncAttributeMaxDynamicSharedMemorySize,
                             CO_SMEM);
        attr_set = true;
    }

    pre_kernel<<<576, 256>>>(H_e, p, H_v, W);
    mult_partial<<<Bb * PAIRS8 * KSPLIT, 256, MULT_SMEM>>>(T);
    combine_out<<<Bb * 64 * 2, 512, CO_SMEM>>>(adj_v);

    int do_he = ((long long)out_size >= (long long)OUT_ELEMS + HE_ELEMS) ? 1 : 0;
    int total = do_he ? (OUT_ELEMS + HE_ELEMS) : OUT_ELEMS;
    out_reduce<<<(total + 255) / 256, 256>>>(bias, H_e, out, do_he);
}

// round 17
// speedup vs baseline: 1.0454x; 1.0006x over previous
#include <cuda_runtime.h>
#include <cuda_bf16.h>
#include <cstdint>

// Problem constants
#define Bb 2
#define Nn 1024
#define Ee 8192
#define Dd 64
#define NT8 8            // 8 tiles of 128 along N
#define PAIRS8 36        // upper-triangular tile pairs
#define KC 32            // K elements per stage
#define KSPLIT 4
#define KQ (Ee / KSPLIT)           // 2048
#define NCHUNK (KQ / KC)           // 64

// ---------------------------------------------------------------------------
// Device scratch
// ---------------------------------------------------------------------------
__device__ float g_scale[Bb * Ee];
__device__ float g_hw[Bb * Nn * Dd];
__device__ float g_part[(size_t)Bb * PAIRS8 * KSPLIT * 128 * 128];
__device__ float g_outp16[16][Bb * Nn * Dd];

// ---------------------------------------------------------------------------
// Portable PTX helpers
// ---------------------------------------------------------------------------
__device__ __forceinline__ uint32_t smem_u32(const void* p) {
    uint32_t a;
    asm("{ .reg .u64 t; cvta.to.shared.u64 t, %1; cvt.u32.u64 %0, t; }" : "=r"(a) : "l"(p));
    return a;
}
#define CP16(dst, src) \
    asm volatile("cp.async.cg.shared.global [%0], [%1], 16;" :: "r"(dst), "l"(src))
#define CP_COMMIT() asm volatile("cp.async.commit_group;")
#define CP_WAIT0()  asm volatile("cp.async.wait_group 0;")
#define CP_WAIT1()  asm volatile("cp.async.wait_group 1;")

__device__ __forceinline__ void ldsm4(uint32_t* r, uint32_t addr) {
    asm volatile("ldmatrix.sync.aligned.m8n8.x4.shared.b16 {%0,%1,%2,%3}, [%4];"
                 : "=r"(r[0]), "=r"(r[1]), "=r"(r[2]), "=r"(r[3]) : "r"(addr));
}
__device__ __forceinline__ void mma_tf32(float* c, const uint32_t* a, const uint32_t* b) {
    asm volatile(
        "mma.sync.aligned.m16n8k8.row.col.f32.tf32.tf32.f32 "
        "{%0,%1,%2,%3}, {%4,%5,%6,%7}, {%8,%9}, {%0,%1,%2,%3};"
        : "+f"(c[0]), "+f"(c[1]), "+f"(c[2]), "+f"(c[3])
        : "r"(a[0]), "r"(a[1]), "r"(a[2]), "r"(a[3]), "r"(b[0]), "r"(b[1]));
}

// ---------------------------------------------------------------------------
// scale[b,e] = dot(H_e[b,e,:], p)   (critical path: mult depends on this)
// ---------------------------------------------------------------------------
__global__ void scale_kernel(const float* __restrict__ H_e,
                             const float* __restrict__ p) {
    __shared__ float ps[64];
    if (threadIdx.x < 64) ps[threadIdx.x] = p[threadIdx.x];
    __syncthreads();
    int r = blockIdx.x * blockDim.x + threadIdx.x;
    if (r < Bb * Ee) {
        const float4* he = reinterpret_cast<const float4*>(H_e + (size_t)r * 64);
        float s = 0.f;
#pragma unroll
        for (int i = 0; i < 16; i++) {
            float4 v = he[i];
            s += v.x * ps[i * 4 + 0] + v.y * ps[i * 4 + 1] +
                 v.z * ps[i * 4 + 2] + v.w * ps[i * 4 + 3];
        }
        g_scale[r] = s;
    }
}

// ---------------------------------------------------------------------------
// hw_kernel: HW = H_v @ W  (side stream; only combine needs it)
// ---------------------------------------------------------------------------
__global__ void hw_kernel(const float* __restrict__ H_v,
                          const float* __restrict__ W) {
    __shared__ float ws[64 * 64];
    __shared__ float hv[4][64];
    int tx = threadIdx.x, ty = threadIdx.y;
    int tid = ty * 64 + tx;
    for (int i = tid; i < 64 * 64; i += 256) ws[i] = W[i];
    int row0 = blockIdx.x * 4;
    hv[ty][tx] = H_v[(size_t)(row0 + ty) * 64 + tx];
    __syncthreads();
    float acc = 0.f;
#pragma unroll
    for (int k = 0; k < 64; k++) acc += hv[ty][k] * ws[k * 64 + tx];
    g_hw[(size_t)(row0 + ty) * 64 + tx] = acc;
}

// ---------------------------------------------------------------------------
// he_copy: second tuple output (H_e pass-through) — fully independent
// ---------------------------------------------------------------------------
#define OUT_ELEMS (Bb * Nn * Dd)               // 131072
#define HE_ELEMS (Bb * Ee * 64)                // 1048576

__global__ void he_copy(const float* __restrict__ H_e, float* __restrict__ out) {
    int i = blockIdx.x * 256 + threadIdx.x;    // float4 index
    if (i < HE_ELEMS / 4)
        reinterpret_cast<float4*>(out + OUT_ELEMS)[i] =
            reinterpret_cast<const float4*>(H_e)[i];
}

// ---------------------------------------------------------------------------
// mult partial (R16-proven): 128x128 tile, quarter-K per CTA, tf32 m16n8k8.
// Raw f32 T for both tiles; per-k scale applied to the B fragments in regs.
// grid = Bb*PAIRS8*KSPLIT = 288 (~2 CTAs/SM), 256 threads, warp grid 2x4.
// ---------------------------------------------------------------------------
#define STRIDE_W 36
#define STAGE_WORDS (128 * STRIDE_W)           // per array: 4608 words
#define OFF_B_BYTES (STAGE_WORDS * 4)          // 18432
#define OFF_S_BYTES (2 * STAGE_WORDS * 4)      // 36864 (32-float s block)
#define STAGE_BYTES (OFF_S_BYTES + 128)        // 36992
#define MULT_SMEM (3 * STAGE_BYTES)            // 110976
#define ROWB (STRIDE_W * 4)                    // 144 bytes per row
#define MTSTEP (16 * ROWB)                     // 2304 bytes per 16-row block

__global__ void __launch_bounds__(256, 2)
mult_partial(const float* __restrict__ T) {
    extern __shared__ __align__(16) char smraw[];
    uint32_t stg = smem_u32(smraw);

    int tid = threadIdx.x;
    int wid = tid >> 5;
    int lid = tid & 31;
    int wm = wid & 1;
    int wn = wid >> 1;

    int p2 = blockIdx.x;
    int pair = p2 >> 2;
    int ksp = p2 & 3;
    int b = pair / PAIRS8;
    int t = pair % PAIRS8;
    int ti = 0, rem = t;
    while (rem >= NT8 - ti) { rem -= NT8 - ti; ti++; }
    int tj = ti + rem;

    size_t rowA = (size_t)(b * Nn + ti * 128);
    size_t rowB = (size_t)(b * Nn + tj * 128);
    int kbase = ksp * KQ;
    const float* scg = g_scale + b * Ee;

    auto load_stage = [&](int sidx, int k0) {
        uint32_t sb = stg + sidx * STAGE_BYTES;
#pragma unroll
        for (int i = 0; i < 4; i++) {
            int chunk = tid + i * 256;
            int row = chunk >> 3, cc = chunk & 7;
            uint32_t d = (uint32_t)(row * ROWB + cc * 16);
            CP16(sb + d, T + (rowA + row) * (size_t)Ee + k0 + cc * 4);
            CP16(sb + OFF_B_BYTES + d, T + (rowB + row) * (size_t)Ee + k0 + cc * 4);
        }
        if (tid < 8)
            CP16(sb + OFF_S_BYTES + tid * 16, scg + k0 + tid * 4);
        CP_COMMIT();
    };

    float acc[4][4][4];
#pragma unroll
    for (int i = 0; i < 4; i++)
#pragma unroll
        for (int j = 0; j < 4; j++)
#pragma unroll
            for (int q = 0; q < 4; q++) acc[i][j][q] = 0.f;

    load_stage(0, kbase);
    load_stage(1, kbase + KC);

    uint32_t a_lane = (uint32_t)(((lid & 7) + ((lid >> 3) & 1) * 8) * ROWB +
                                 (lid >> 4) * 16);
    uint32_t b_lane = (uint32_t)((((lid >> 4) * 8) + (lid & 7)) * ROWB +
                                 (((lid >> 3) & 1) * 16));
    uint32_t a_base0 = (uint32_t)(wm * 64 * ROWB) + a_lane;
    uint32_t b_base0 = (uint32_t)OFF_B_BYTES + (uint32_t)(wn * 32 * ROWB) + b_lane;
    int skc = lid & 3;

    for (int s = 0; s < NCHUNK; s++) {
        if (s < NCHUNK - 1) CP_WAIT1(); else CP_WAIT0();
        __syncthreads();
        uint32_t sb = stg + (s % 3) * STAGE_BYTES;
        uint32_t ab = sb + a_base0;
        uint32_t bb = sb + b_base0;
        const float* sS = reinterpret_cast<const float*>(
            smraw + (size_t)(sb - stg) + OFF_S_BYTES);

#pragma unroll
        for (int ks = 0; ks < 4; ks++) {
            float sv0 = sS[ks * 8 + skc];
            float sv1 = sS[ks * 8 + 4 + skc];
            uint32_t af[4][4], bq[2][4];
#pragma unroll
            for (int mt = 0; mt < 4; mt++)
                ldsm4(af[mt], ab + mt * MTSTEP + ks * 32);
#pragma unroll
            for (int ntp = 0; ntp < 2; ntp++)
                ldsm4(bq[ntp], bb + ntp * MTSTEP + ks * 32);
#pragma unroll
            for (int ntp = 0; ntp < 2; ntp++) {
                bq[ntp][0] = __float_as_uint(__uint_as_float(bq[ntp][0]) * sv0);
                bq[ntp][1] = __float_as_uint(__uint_as_float(bq[ntp][1]) * sv1);
                bq[ntp][2] = __float_as_uint(__uint_as_float(bq[ntp][2]) * sv0);
                bq[ntp][3] = __float_as_uint(__uint_as_float(bq[ntp][3]) * sv1);
            }
#pragma unroll
            for (int mt = 0; mt < 4; mt++)
#pragma unroll
                for (int nt = 0; nt < 4; nt++)
                    mma_tf32(acc[mt][nt], af[mt], &bq[nt >> 1][(nt & 1) * 2]);
        }
        if (s + 2 < NCHUNK) load_stage((s + 2) % 3, kbase + (s + 2) * KC);
    }

    float* pt = g_part + (size_t)p2 * 128 * 128;
#pragma unroll
    for (int mt = 0; mt < 4; mt++)
#pragma unroll
        for (int nt = 0; nt < 4; nt++) {
            int r = wm * 64 + mt * 16 + (lid >> 2);
            int c = wn * 32 + nt * 8 + (lid & 3) * 2;
            *reinterpret_cast<float2*>(pt + (size_t)r * 128 + c) =
                make_float2(acc[mt][nt][0], acc[mt][nt][1]);
            *reinterpret_cast<float2*>(pt + (size_t)(r + 8) * 128 + c) =
                make_float2(acc[mt][nt][2], acc[mt][nt][3]);
        }
}

// ---------------------------------------------------------------------------
// combine_out (R14/R16-proven): per (b, i, j, kh). grid = 256, 512 thr.
// ---------------------------------------------------------------------------
#define CO_SMEM (64 * 132 * 4 + 64 * 68 * 4)

__global__ void __launch_bounds__(512, 2)
combine_out(const float* __restrict__ adj_v) {
    extern __shared__ float cs[];
    float* vs = cs;                      // [k][r] stride 132 (k local 0..63)
    float* HWs = cs + 64 * 132;          // [k][d] stride 68

    int tid = threadIdx.x;
    int bid = blockIdx.x;
    int b = bid >> 7;
    int r2 = bid & 127;
    int ij = r2 >> 1, kh = r2 & 1;
    int i = ij >> 3, j = ij & 7;

    const float* HWb = g_hw + (size_t)b * Nn * Dd + (size_t)(j * 128 + kh * 64) * 64;
    for (int idx = tid; idx < 4096; idx += 512)
        HWs[(idx >> 6) * 68 + (idx & 63)] = HWb[idx];

    int lo = i < j ? i : j, hi = i < j ? j : i;
    int p = 8 * lo - lo * (lo - 1) / 2 + (hi - lo);
    const float* p0 = g_part + ((size_t)(b * PAIRS8 + p) * 4 + 0) * 16384;
    const float* p1 = g_part + ((size_t)(b * PAIRS8 + p) * 4 + 1) * 16384;
    const float* p2 = g_part + ((size_t)(b * PAIRS8 + p) * 4 + 2) * 16384;
    const float* p3 = g_part + ((size_t)(b * PAIRS8 + p) * 4 + 3) * 16384;

    if (i <= j) {
        for (int idx = tid; idx < 8192; idx += 512) {
            int r = idx >> 6, c = idx & 63;
            int src = r * 128 + kh * 64 + c;
            vs[c * 132 + r] = (p0[src] + p1[src]) + (p2[src] + p3[src]);
        }
    } else {
        for (int idx = tid; idx < 8192; idx += 512) {
            int rp = idx >> 7, cp = idx & 127;
            int src = (kh * 64 + rp) * 128 + cp;
            vs[rp * 132 + cp] = (p0[src] + p1[src]) + (p2[src] + p3[src]);
        }
    }
    __syncthreads();

    const float* av = adj_v + (size_t)b * Nn * Nn;
    for (int idx = tid; idx < 8192; idx += 512) {
        int r = idx >> 6, c = idx & 63;
        int n = i * 128 + r, mcol = j * 128 + kh * 64 + c;
        float m = vs[c * 132 + r];
        if (i == j && r == kh * 64 + c) m = 1.f;
        vs[c * 132 + r] = m * av[(size_t)n * Nn + mcol];
    }
    __syncthreads();

    int rq = tid & 31;
    int cq = tid >> 5;
    float o[4][4];
#pragma unroll
    for (int r = 0; r < 4; r++)
#pragma unroll
        for (int c = 0; c < 4; c++) o[r][c] = 0.f;

    for (int k = 0; k < 64; k++) {
        float4 h = *reinterpret_cast<float4*>(&HWs[k * 68 + cq * 4]);
        float4 v = *reinterpret_cast<float4*>(&vs[k * 132 + rq * 4]);
        float vv[4] = {v.x, v.y, v.z, v.w};
#pragma unroll
        for (int r = 0; r < 4; r++) {
            o[r][0] += vv[r] * h.x; o[r][1] += vv[r] * h.y;
            o[r][2] += vv[r] * h.z; o[r][3] += vv[r] * h.w;
        }
    }

    float* os = g_outp16[j * 2 + kh] + ((size_t)b * Nn + i * 128) * 64;
#pragma unroll
    for (int r = 0; r < 4; r++)
        *reinterpret_cast<float4*>(&os[(size_t)(rq * 4 + r) * 64 + cq * 4]) =
            make_float4(o[r][0], o[r][1], o[r][2], o[r][3]);
}

// ---------------------------------------------------------------------------
// out_reduce: sum 16 slots + bias (H_e copy moved to side stream)
// ---------------------------------------------------------------------------
__global__ void out_reduce(const float* __restrict__ bias, float* __restrict__ out) {
    int idx = blockIdx.x * 256 + threadIdx.x;
    if (idx < OUT_ELEMS) {
        float s = bias[idx & 63];
#pragma unroll
        for (int q = 0; q < 16; q++) s += g_outp16[q][idx];
        out[idx] = s;
    }
}

// ---------------------------------------------------------------------------
extern "C" void kernel_launch(void* const* d_in, const int* in_sizes, int n_in,
                              void* d_out, int out_size) {
    const float* H_v   = (const float*)d_in[0];
    const float* H_e   = (const float*)d_in[1];
    // d_in[2] = adj_e : unused by the reference math
    const float* adj_v = (const float*)d_in[3];
    const float* T     = (const float*)d_in[4];
    const float* W     = (const float*)d_in[5];
    const float* p     = (const float*)d_in[6];
    const float* bias  = (const float*)d_in[7];
    float* out = (float*)d_out;

    static cudaStream_t s1 = nullptr;
    static cudaEvent_t eFork = nullptr, eJoin = nullptr;
    static bool init_done = false;
    if (!init_done) {
        cudaFuncSetAttribute(mult_partial, cudaFuncAttributeMaxDynamicSharedMemorySize,
                             MULT_SMEM);
        cudaFuncSetAttribute(combine_out, cudaFuncAttributeMaxDynamicSharedMemorySize,
                             CO_SMEM);
        cudaStreamCreateWithFlags(&s1, cudaStreamNonBlocking);
        cudaEventCreateWithFlags(&eFork, cudaEventDisableTiming);
        cudaEventCreateWithFlags(&eJoin, cudaEventDisableTiming);
        init_done = true;
    }

    int do_he = ((long long)out_size >= (long long)OUT_ELEMS + HE_ELEMS) ? 1 : 0;

    // Critical path (default stream): scale -> mult -> combine -> reduce
    scale_kernel<<<(Bb * Ee + 255) / 256, 256>>>(H_e, p);

    // Fork side stream: hw (needed by combine) + H_e pass-through copy
    cudaEventRecord(eFork, 0);
    cudaStreamWaitEvent(s1, eFork, 0);
    hw_kernel<<<(Bb * Nn) / 4, dim3(64, 4), 0, s1>>>(H_v, W);
    if (do_he)
        he_copy<<<(HE_ELEMS / 4 + 255) / 256, 256, 0, s1>>>(H_e, out);
    cudaEventRecord(eJoin, s1);

    mult_partial<<<Bb * PAIRS8 * KSPLIT, 256, MULT_SMEM>>>(T);

    // Join before combine (combine reads g_hw)
    cudaStreamWaitEvent(0, eJoin, 0);
    combine_out<<<Bb * 64 * 2, 512, CO_SMEM>>>(adj_v);
    out_reduce<<<(OUT_ELEMS + 255) / 256, 256>>>(bias, out);
}